// round 15
// baseline (speedup 1.0000x reference)
#include <cuda_runtime.h>
#include <cstdint>
#include <cuda_fp16.h>

#define NPIX   6400
#define SCALE  0.17677669529663687f   // 32^-0.5

// Scratch (device globals), all fp16 channel-pair packed: word (c2, n) =
// half2(ch 2*c2, ch 2*c2+1) at pixel n. +16 words padding for vector overread.
__device__ __align__(16) uint32_t g_qkv16 [4 * 384 * 6400 + 16]; // q|k|v planes
__device__ __align__(16) uint32_t g_attn16[4 * 128 * 6400 + 16];
__device__ __align__(16) uint32_t g_y16   [4 * 128 * 6400];
__device__ uint32_t g_wq16[768 * 128];   // packed fp16, k-interleaved
__device__ uint32_t g_wp16[256 * 128];

// ---------------------------------------------------------------------------
// Helpers (sm_80-class PTX only: family-safe on compute_103)
// ---------------------------------------------------------------------------
__device__ __forceinline__ uint32_t smem_u32(const void* p) {
    uint32_t a;
    asm("{ .reg .u64 t; cvta.to.shared.u64 t, %1; cvt.u32.u64 %0, t; }" : "=r"(a) : "l"(p));
    return a;
}
__device__ __forceinline__ void cp16(uint32_t dst, const void* src) {
    asm volatile("cp.async.cg.shared.global [%0], [%1], 16;" :: "r"(dst), "l"(src));
}
#define CP_COMMIT() asm volatile("cp.async.commit_group;" ::: "memory")
#define CP_WAIT2()  asm volatile("cp.async.wait_group 2;" ::: "memory")

__device__ __forceinline__ uint32_t packh2(float a, float b) {
    __half2 h = __floats2half2_rn(a, b);          // a -> low half
    return *reinterpret_cast<uint32_t*>(&h);
}
__device__ __forceinline__ float2 unpackh2(uint32_t w) {
    return __half22float2(*reinterpret_cast<__half2*>(&w));
}
__device__ __forceinline__ void mma_f16(float c[4],
                                        uint32_t a0, uint32_t a1, uint32_t a2, uint32_t a3,
                                        uint32_t b0, uint32_t b1) {
    asm volatile("mma.sync.aligned.m16n8k16.row.col.f32.f16.f16.f32 "
                 "{%0,%1,%2,%3}, {%4,%5,%6,%7}, {%8,%9}, {%0,%1,%2,%3};"
                 : "+f"(c[0]), "+f"(c[1]), "+f"(c[2]), "+f"(c[3])
                 : "r"(a0), "r"(a1), "r"(a2), "r"(a3), "r"(b0), "r"(b1));
}

// Smem (per stage, uint32 words): A [128 o][24] (16 words + pad), B [16][136]
#define AS_W    24
#define AS_SZ   (128 * AS_W)
#define BS_W    136
#define BS_SZ   (16 * BS_W)
#define STAGE_W (AS_SZ + BS_SZ)          // 5248 words = 20992 B
#define SMEM_BYTES (3 * STAGE_W * 4)     // 62976 B (3 stages)

// ---------------------------------------------------------------------------
// Fused prologue: y -> packed fp16 [b][c2][n]  (blockIdx.y < 128),
// weights -> packed fp16, 8-group k-interleaved (blockIdx.y == 128 strip).
// ---------------------------------------------------------------------------
__global__ __launch_bounds__(256) void conv_all(const float* __restrict__ rgb,
                                                const float* __restrict__ ir,
                                                const float* __restrict__ wq,
                                                const float* __restrict__ wp)
{
    const int c2 = blockIdx.y;
    if (c2 < 128) {
        const int n = blockIdx.x * 256 + threadIdx.x;
        const int b = blockIdx.z;
        const float* src = (c2 < 64)
            ? rgb + ((size_t)b * 128 + 2 * c2) * NPIX
            : ir  + ((size_t)b * 128 + 2 * (c2 - 64)) * NPIX;
        g_y16[((size_t)b * 128 + c2) * NPIX + n] = packh2(src[n], src[NPIX + n]);
    } else if (blockIdx.z == 0) {
        // weight strip: 25 blocks x 256 thr x (2 rows each) covers 1024 rows x 128 words
        const int idx = blockIdx.x * 512 + threadIdx.x * 2;   // 2 rows per thread
        #pragma unroll
        for (int t = 0; t < 2; t++) {
            const int row = idx + t;                          // 0..1023
            if (row >= 1024) break;
            for (int j = 0; j < 128; j++) {
                const int jp = (j & ~7) | (((j & 3) << 1) | ((j >> 2) & 1));
                if (row < 768)
                    g_wq16[row * 128 + jp] = packh2(wq[row * 256 + 2 * j],
                                                    wq[row * 256 + 2 * j + 1]);
                else
                    g_wp16[(row - 768) * 128 + jp] = packh2(wp[(row - 768) * 256 + 2 * j],
                                                            wp[(row - 768) * 256 + 2 * j + 1]);
            }
        }
    }
}

// ---------------------------------------------------------------------------
// GEMM k-tile (32 k = 16 words): warp grid 2(m) x 4(n), warp tile 64 x 32.
// ---------------------------------------------------------------------------
__device__ __forceinline__ void gemm_ktile16(const uint32_t* As, const uint32_t* Bs,
                                             int wm0, int wn0, int row, int colk,
                                             float acc[4][4][4]) {
    #pragma unroll
    for (int ks = 0; ks < 2; ks++) {
        const int kb = ks * 8;
        uint32_t a[4][4], bfr[4][2];
        #pragma unroll
        for (int mt = 0; mt < 4; mt++) {
            const uint32_t* ab = As + (wm0 + mt * 16 + row) * AS_W + kb + 2 * colk;
            uint2 lo = *(const uint2*)ab;
            uint2 hi = *(const uint2*)(ab + 8 * AS_W);
            a[mt][0] = lo.x; a[mt][1] = hi.x; a[mt][2] = lo.y; a[mt][3] = hi.y;
        }
        #pragma unroll
        for (int nt = 0; nt < 4; nt++) {
            const uint32_t* bb = Bs + (kb + colk) * BS_W + wn0 + nt * 8 + row;
            bfr[nt][0] = bb[0];
            bfr[nt][1] = bb[4 * BS_W];
        }
        #pragma unroll
        for (int mt = 0; mt < 4; mt++)
            #pragma unroll
            for (int nt = 0; nt < 4; nt++)
                mma_f16(acc[mt][nt], a[mt][0], a[mt][1], a[mt][2], a[mt][3],
                        bfr[nt][0], bfr[nt][1]);
    }
}

// ---------------------------------------------------------------------------
// Kernel A: qkv (fp16 MMA), 256 threads / 128x128 tile, 3-stage pipeline.
// Grid: x = o-tile (fast, 6), y = n-tile (50) -> wave covers all o per n-tile.
// ---------------------------------------------------------------------------
__global__ __launch_bounds__(256, 2) void qkv_gemm()
{
    extern __shared__ __align__(16) uint32_t buf[];

    const int b  = blockIdx.z;
    const int n0 = blockIdx.y * 128;
    const int m0 = blockIdx.x * 128;
    const int tid = threadIdx.x;
    const int wid = tid >> 5, lane = tid & 31;
    const int wm0 = (wid >> 2) * 64, wn0 = (wid & 3) * 32;
    const int row = lane >> 2, colk = lane & 3;

    const uint32_t* yb = g_y16 + (size_t)b * 128 * NPIX;
    const uint32_t sbase = smem_u32(buf);

    auto load_tile = [&](int kt, int stage) {
        const int kw0 = kt * 16;
        const uint32_t As = sbase + stage * STAGE_W * 4;
        const uint32_t Bs = As + AS_SZ * 4;
        #pragma unroll
        for (int j = 0; j < 2; j++) {
            int idx = tid + 256 * j;
            int ar = idx >> 2, ac = (idx & 3) * 4;
            cp16(As + (ar * AS_W + ac) * 4, g_wq16 + (size_t)(m0 + ar) * 128 + kw0 + ac);
        }
        #pragma unroll
        for (int j = 0; j < 2; j++) {
            int idx = tid + 256 * j;
            int bk = idx >> 5, bnc = (idx & 31) * 4;
            cp16(Bs + (bk * BS_W + bnc) * 4, yb + (size_t)(kw0 + bk) * NPIX + n0 + bnc);
        }
    };

    float acc[4][4][4];
    #pragma unroll
    for (int mt = 0; mt < 4; mt++)
        #pragma unroll
        for (int nt = 0; nt < 4; nt++)
            #pragma unroll
            for (int i = 0; i < 4; i++) acc[mt][nt][i] = 0.f;

    load_tile(0, 0); CP_COMMIT();
    load_tile(1, 1); CP_COMMIT();
    load_tile(2, 2); CP_COMMIT();

    #pragma unroll
    for (int kt = 0; kt < 8; kt++) {
        CP_WAIT2();
        __syncthreads();
        const int st = kt % 3;
        const uint32_t* As = buf + st * STAGE_W;
        const uint32_t* Bs = As + AS_SZ;
        gemm_ktile16(As, Bs, wm0, wn0, row, colk, acc);
        __syncthreads();
        if (kt + 3 < 8) load_tile(kt + 3, st);
        CP_COMMIT();
    }

    // Epilogue: pair adjacent o rows via shfl, write packed fp16 [b][c2][n].
    uint32_t* outb = g_qkv16 + (size_t)b * 384 * NPIX;
    const bool evenrow = ((row & 1) == 0);
    #pragma unroll
    for (int mt = 0; mt < 4; mt++) {
        #pragma unroll
        for (int nt = 0; nt < 4; nt++) {
            const int o = m0 + wm0 + mt * 16 + row;
            const int n = n0 + wn0 + nt * 8 + 2 * colk;
            float p0 = __shfl_down_sync(0xFFFFFFFFu, acc[mt][nt][0], 4);
            float p1 = __shfl_down_sync(0xFFFFFFFFu, acc[mt][nt][1], 4);
            float p2 = __shfl_down_sync(0xFFFFFFFFu, acc[mt][nt][2], 4);
            float p3 = __shfl_down_sync(0xFFFFFFFFu, acc[mt][nt][3], 4);
            if (evenrow) {
                uint2 w0 = make_uint2(packh2(acc[mt][nt][0], p0),
                                      packh2(acc[mt][nt][1], p1));
                *(uint2*)(outb + (size_t)(o >> 1) * NPIX + n) = w0;
                uint2 w1 = make_uint2(packh2(acc[mt][nt][2], p2),
                                      packh2(acc[mt][nt][3], p3));
                *(uint2*)(outb + (size_t)((o >> 1) + 4) * NPIX + n) = w1;
            }
        }
    }
}

// ---------------------------------------------------------------------------
// Kernel B: dilated local attention on packed fp16 qkv (round-12 config).
// 128-thread blocks. 2 pixels/thread; hd halves across lane pairs (xor 16).
// ---------------------------------------------------------------------------
__global__ __launch_bounds__(128, 5) void attn_kernel()
{
    const int tid  = threadIdx.x;
    const int wid  = tid >> 5, lane = tid & 31;
    const int half = lane >> 4;
    const int pp   = blockIdx.x * 64 + wid * 16 + (lane & 15);
    const int n    = pp * 2;
    const int dh   = blockIdx.y;
    const int dil  = dh >> 2;
    const int head = dh & 3;
    const int b    = blockIdx.z;
    const int d    = dil ? 3 : 2;

    const int r = n / 80;
    const int c = n % 80;

    const uint32_t* qb = g_qkv16
        + ((size_t)(b * 384 + dil * 64 + head * 16 + half * 8)) * NPIX + n;
    const uint32_t* kb = qb + (size_t)128 * NPIX;
    const uint32_t* vb = qb + (size_t)256 * NPIX;

    float2 qx[8], qy[8];
    #pragma unroll
    for (int j = 0; j < 8; j++) {
        uint2 w = *(const uint2*)(qb + j * NPIX);
        qx[j] = unpackh2(w.x);
        qy[j] = unpackh2(w.y);
    }

    float scx[9], scy[9];
    #pragma unroll
    for (int jj = 0; jj < 9; jj++) {
        const int di = jj / 3 - 1, dj = jj % 3 - 1;
        const int rr = r + di * d;
        const int cc0 = c + dj * d, cc1 = cc0 + 1;
        const bool v0 = (cc0 >= 0 && cc0 < 80);
        const bool v1 = (cc1 >= 0 && cc1 < 80);
        float sx = 0.f, sy = 0.f;
        if (rr >= 0 && rr < 80 && (v0 || v1)) {
            const int off = di * d * 80 + dj * d;
            const uint32_t* kp = kb + off;
            if ((off & 1) == 0) {
                #pragma unroll
                for (int j = 0; j < 8; j++) {
                    uint2 w = *(const uint2*)(kp + j * NPIX);
                    float2 k0 = unpackh2(w.x), k1 = unpackh2(w.y);
                    sx = fmaf(qx[j].x, k0.x, sx); sx = fmaf(qx[j].y, k0.y, sx);
                    sy = fmaf(qy[j].x, k1.x, sy); sy = fmaf(qy[j].y, k1.y, sy);
                }
            } else {
                #pragma unroll
                for (int j = 0; j < 8; j++) {
                    float2 k0 = unpackh2(kp[j * NPIX]);
                    float2 k1 = unpackh2(kp[j * NPIX + 1]);
                    sx = fmaf(qx[j].x, k0.x, sx); sx = fmaf(qx[j].y, k0.y, sx);
                    sy = fmaf(qy[j].x, k1.x, sy); sy = fmaf(qy[j].y, k1.y, sy);
                }
            }
            if (!v0) sx = 0.f;
            if (!v1) sy = 0.f;
        }
        sx += __shfl_xor_sync(0xFFFFFFFFu, sx, 16);
        sy += __shfl_xor_sync(0xFFFFFFFFu, sy, 16);
        scx[jj] = sx * SCALE;
        scy[jj] = sy * SCALE;
    }

    float mx = scx[0], my = scy[0];
    #pragma unroll
    for (int jj = 1; jj < 9; jj++) { mx = fmaxf(mx, scx[jj]); my = fmaxf(my, scy[jj]); }
    float sumx = 0.f, sumy = 0.f;
    #pragma unroll
    for (int jj = 0; jj < 9; jj++) {
        scx[jj] = __expf(scx[jj] - mx); sumx += scx[jj];
        scy[jj] = __expf(scy[jj] - my); sumy += scy[jj];
    }
    const float invx = 1.f / sumx, invy = 1.f / sumy;

    float2 ox[8], oy[8];
    #pragma unroll
    for (int j = 0; j < 8; j++) { ox[j] = make_float2(0.f, 0.f); oy[j] = make_float2(0.f, 0.f); }

    #pragma unroll
    for (int jj = 0; jj < 9; jj++) {
        const int di = jj / 3 - 1, dj = jj % 3 - 1;
        const int rr = r + di * d;
        const int cc0 = c + dj * d, cc1 = cc0 + 1;
        const bool v0 = (cc0 >= 0 && cc0 < 80);
        const bool v1 = (cc1 >= 0 && cc1 < 80);
        if (rr >= 0 && rr < 80 && (v0 || v1)) {
            const int off = di * d * 80 + dj * d;
            const float px = v0 ? scx[jj] * invx : 0.f;
            const float py = v1 ? scy[jj] * invy : 0.f;
            const uint32_t* vp = vb + off;
            if ((off & 1) == 0) {
                #pragma unroll
                for (int j = 0; j < 8; j++) {
                    uint2 w = *(const uint2*)(vp + j * NPIX);
                    float2 a0 = unpackh2(w.x), a1 = unpackh2(w.y);
                    ox[j].x = fmaf(px, a0.x, ox[j].x); ox[j].y = fmaf(px, a0.y, ox[j].y);
                    oy[j].x = fmaf(py, a1.x, oy[j].x); oy[j].y = fmaf(py, a1.y, oy[j].y);
                }
            } else {
                #pragma unroll
                for (int j = 0; j < 8; j++) {
                    float2 a0 = unpackh2(vp[j * NPIX]);
                    float2 a1 = unpackh2(vp[j * NPIX + 1]);
                    ox[j].x = fmaf(px, a0.x, ox[j].x); ox[j].y = fmaf(px, a0.y, ox[j].y);
                    oy[j].x = fmaf(py, a1.x, oy[j].x); oy[j].y = fmaf(py, a1.y, oy[j].y);
                }
            }
        }
    }

    uint32_t* ob = g_attn16
        + ((size_t)(b * 128 + dil * 64 + head * 16 + half * 8)) * NPIX + n;
    #pragma unroll
    for (int j = 0; j < 8; j++) {
        uint2 w = make_uint2(packh2(ox[j].x, ox[j].y), packh2(oy[j].x, oy[j].y));
        *(uint2*)(ob + (size_t)j * NPIX) = w;
    }
}

// ---------------------------------------------------------------------------
// Kernel C: proj (fp16 MMA), 256 threads, 3-stage pipeline, fused epilogue.
// ---------------------------------------------------------------------------
__global__ __launch_bounds__(256, 2) void proj_kernel(const float* __restrict__ bias,
                                                      const float* __restrict__ rgb,
                                                      const float* __restrict__ ir,
                                                      float* __restrict__ out)
{
    extern __shared__ __align__(16) uint32_t buf[];

    const int b  = blockIdx.z;
    const int n0 = blockIdx.y * 128;
    const int m0 = blockIdx.x * 128;
    const int tid = threadIdx.x;
    const int wid = tid >> 5, lane = tid & 31;
    const int wm0 = (wid >> 2) * 64, wn0 = (wid & 3) * 32;
    const int row = lane >> 2, colk = lane & 3;

    const uint32_t* ab = g_attn16 + (size_t)b * 128 * NPIX;
    const uint32_t sbase = smem_u32(buf);

    auto load_tile = [&](int kt, int stage) {
        const int kw0 = kt * 16;
        const uint32_t As = sbase + stage * STAGE_W * 4;
        const uint32_t Bs = As + AS_SZ * 4;
        #pragma unroll
        for (int j = 0; j < 2; j++) {
            int idx = tid + 256 * j;
            int ar = idx >> 2, ac = (idx & 3) * 4;
            cp16(As + (ar * AS_W + ac) * 4, g_wp16 + (size_t)(m0 + ar) * 128 + kw0 + ac);
        }
        #pragma unroll
        for (int j = 0; j < 2; j++) {
            int idx = tid + 256 * j;
            int bk = idx >> 5, bnc = (idx & 31) * 4;
            cp16(Bs + (bk * BS_W + bnc) * 4, ab + (size_t)(kw0 + bk) * NPIX + n0 + bnc);
        }
    };

    float acc[4][4][4];
    #pragma unroll
    for (int mt = 0; mt < 4; mt++)
        #pragma unroll
        for (int nt = 0; nt < 4; nt++)
            #pragma unroll
            for (int i = 0; i < 4; i++) acc[mt][nt][i] = 0.f;

    load_tile(0, 0); CP_COMMIT();
    load_tile(1, 1); CP_COMMIT();
    load_tile(2, 2); CP_COMMIT();

    #pragma unroll
    for (int kt = 0; kt < 8; kt++) {
        CP_WAIT2();
        __syncthreads();
        const int st = kt % 3;
        const uint32_t* As = buf + st * STAGE_W;
        const uint32_t* Bs = As + AS_SZ;
        gemm_ktile16(As, Bs, wm0, wn0, row, colk, acc);
        __syncthreads();
        if (kt + 3 < 8) load_tile(kt + 3, st);
        CP_COMMIT();
    }

    const float* resb = ((m0 == 0) ? rgb : ir) + (size_t)b * 128 * NPIX;
    float* outb = out + (size_t)b * NPIX * 256;

    #pragma unroll
    for (int mt = 0; mt < 4; mt++) {
        const int o_lo = m0 + wm0 + mt * 16 + row;
        const int o_hi = o_lo + 8;
        const float bias_lo = __ldg(bias + o_lo);
        const float bias_hi = __ldg(bias + o_hi);
        const float* res_lo = resb + (size_t)(o_lo & 127) * NPIX;
        const float* res_hi = resb + (size_t)(o_hi & 127) * NPIX;
        #pragma unroll
        for (int nt = 0; nt < 4; nt++) {
            const int n = n0 + wn0 + nt * 8 + 2 * colk;
            outb[(size_t)n * 256 + o_lo]       = acc[mt][nt][0] + bias_lo + res_lo[n];
            outb[(size_t)(n + 1) * 256 + o_lo] = acc[mt][nt][1] + bias_lo + res_lo[n + 1];
            outb[(size_t)n * 256 + o_hi]       = acc[mt][nt][2] + bias_hi + res_hi[n];
            outb[(size_t)(n + 1) * 256 + o_hi] = acc[mt][nt][3] + bias_hi + res_hi[n + 1];
        }
    }
}

// ---------------------------------------------------------------------------
extern "C" void kernel_launch(void* const* d_in, const int* in_sizes, int n_in,
                              void* d_out, int out_size)
{
    const float* rgb    = (const float*)d_in[0];
    const float* ir     = (const float*)d_in[1];
    const float* w_qkv  = (const float*)d_in[2];
    const float* w_proj = (const float*)d_in[3];
    const float* b_proj = (const float*)d_in[4];
    float* out = (float*)d_out;

    cudaFuncSetAttribute(qkv_gemm, cudaFuncAttributeMaxDynamicSharedMemorySize, SMEM_BYTES);
    cudaFuncSetAttribute(proj_kernel, cudaFuncAttributeMaxDynamicSharedMemorySize, SMEM_BYTES);

    conv_all<<<dim3(25, 129, 4), 256>>>(rgb, ir, w_qkv, w_proj);
    qkv_gemm<<<dim3(6, 50, 4), 256, SMEM_BYTES>>>();
    attn_kernel<<<dim3(50, 8, 4), 128>>>();
    proj_kernel<<<dim3(2, 50, 4), 256, SMEM_BYTES>>>(b_proj, rgb, ir, out);
}

// round 16
// speedup vs baseline: 2.1943x; 2.1943x over previous
#include <cuda_runtime.h>
#include <cstdint>
#include <cuda_fp16.h>

#define NPIX   6400
#define SCALE  0.17677669529663687f   // 32^-0.5

// Scratch (device globals), all fp16 channel-pair packed: word (c2, n) =
// half2(ch 2*c2, ch 2*c2+1) at pixel n. +16 words padding for vector overread.
__device__ __align__(16) uint32_t g_qkv16 [4 * 384 * 6400 + 16]; // q|k|v planes
__device__ __align__(16) uint32_t g_attn16[4 * 128 * 6400 + 16];
__device__ __align__(16) uint32_t g_y16   [4 * 128 * 6400];
__device__ uint32_t g_wq16[768 * 128];   // packed fp16, k-interleaved
__device__ uint32_t g_wp16[256 * 128];

// ---------------------------------------------------------------------------
// Helpers (sm_80-class PTX only: family-safe on compute_103)
// ---------------------------------------------------------------------------
__device__ __forceinline__ uint32_t smem_u32(const void* p) {
    uint32_t a;
    asm("{ .reg .u64 t; cvta.to.shared.u64 t, %1; cvt.u32.u64 %0, t; }" : "=r"(a) : "l"(p));
    return a;
}
__device__ __forceinline__ void cp16(uint32_t dst, const void* src) {
    asm volatile("cp.async.cg.shared.global [%0], [%1], 16;" :: "r"(dst), "l"(src));
}
#define CP_COMMIT() asm volatile("cp.async.commit_group;" ::: "memory")
#define CP_WAIT2()  asm volatile("cp.async.wait_group 2;" ::: "memory")

__device__ __forceinline__ uint32_t packh2(float a, float b) {
    __half2 h = __floats2half2_rn(a, b);          // a -> low half
    return *reinterpret_cast<uint32_t*>(&h);
}
__device__ __forceinline__ float2 unpackh2(uint32_t w) {
    return __half22float2(*reinterpret_cast<__half2*>(&w));
}
__device__ __forceinline__ void mma_f16(float c[4],
                                        uint32_t a0, uint32_t a1, uint32_t a2, uint32_t a3,
                                        uint32_t b0, uint32_t b1) {
    asm volatile("mma.sync.aligned.m16n8k16.row.col.f32.f16.f16.f32 "
                 "{%0,%1,%2,%3}, {%4,%5,%6,%7}, {%8,%9}, {%0,%1,%2,%3};"
                 : "+f"(c[0]), "+f"(c[1]), "+f"(c[2]), "+f"(c[3])
                 : "r"(a0), "r"(a1), "r"(a2), "r"(a3), "r"(b0), "r"(b1));
}

// Smem (per stage, uint32 words): A [128 o][24] (16 words + pad), B [16][136]
#define AS_W    24
#define AS_SZ   (128 * AS_W)
#define BS_W    136
#define BS_SZ   (16 * BS_W)
#define STAGE_W (AS_SZ + BS_SZ)          // 5248 words = 20992 B
#define SMEM_BYTES (3 * STAGE_W * 4)     // 62976 B (3 stages)

// ---------------------------------------------------------------------------
// Prologue 1: weights -> packed fp16 words, 8-group interleaved.
// ---------------------------------------------------------------------------
__global__ __launch_bounds__(128) void conv_w(const float* __restrict__ wq,
                                              const float* __restrict__ wp)
{
    const int row = blockIdx.x;          // 0..1023 : 0..767 wq, 768..1023 wp
    const int j   = threadIdx.x;
    const int jp  = (j & ~7) | (((j & 3) << 1) | ((j >> 2) & 1));
    if (row < 768) {
        g_wq16[row * 128 + jp] = packh2(wq[row * 256 + 2 * j], wq[row * 256 + 2 * j + 1]);
    } else {
        int r = row - 768;
        g_wp16[r * 128 + jp] = packh2(wp[r * 256 + 2 * j], wp[r * 256 + 2 * j + 1]);
    }
}

// ---------------------------------------------------------------------------
// Prologue 2: y = concat(rgb, ir) -> packed fp16 words [b][c2][n]
// ---------------------------------------------------------------------------
__global__ __launch_bounds__(256) void conv_y16(const float* __restrict__ rgb,
                                                const float* __restrict__ ir)
{
    const int n  = blockIdx.x * 256 + threadIdx.x;
    const int c2 = blockIdx.y;
    const int b  = blockIdx.z;
    const float* src = (c2 < 64)
        ? rgb + ((size_t)b * 128 + 2 * c2) * NPIX
        : ir  + ((size_t)b * 128 + 2 * (c2 - 64)) * NPIX;
    g_y16[((size_t)b * 128 + c2) * NPIX + n] = packh2(src[n], src[NPIX + n]);
}

// ---------------------------------------------------------------------------
// GEMM k-tile (32 k = 16 words): warp grid 2(m) x 4(n), warp tile 64 x 32.
// ---------------------------------------------------------------------------
__device__ __forceinline__ void gemm_ktile16(const uint32_t* As, const uint32_t* Bs,
                                             int wm0, int wn0, int row, int colk,
                                             float acc[4][4][4]) {
    #pragma unroll
    for (int ks = 0; ks < 2; ks++) {
        const int kb = ks * 8;
        uint32_t a[4][4], bfr[4][2];
        #pragma unroll
        for (int mt = 0; mt < 4; mt++) {
            const uint32_t* ab = As + (wm0 + mt * 16 + row) * AS_W + kb + 2 * colk;
            uint2 lo = *(const uint2*)ab;
            uint2 hi = *(const uint2*)(ab + 8 * AS_W);
            a[mt][0] = lo.x; a[mt][1] = hi.x; a[mt][2] = lo.y; a[mt][3] = hi.y;
        }
        #pragma unroll
        for (int nt = 0; nt < 4; nt++) {
            const uint32_t* bb = Bs + (kb + colk) * BS_W + wn0 + nt * 8 + row;
            bfr[nt][0] = bb[0];
            bfr[nt][1] = bb[4 * BS_W];
        }
        #pragma unroll
        for (int mt = 0; mt < 4; mt++)
            #pragma unroll
            for (int nt = 0; nt < 4; nt++)
                mma_f16(acc[mt][nt], a[mt][0], a[mt][1], a[mt][2], a[mt][3],
                        bfr[nt][0], bfr[nt][1]);
    }
}

// ---------------------------------------------------------------------------
// Kernel A: qkv (fp16 MMA), 256 threads / 128x128 tile, 3-stage pipeline.
// ---------------------------------------------------------------------------
__global__ __launch_bounds__(256, 2) void qkv_gemm()
{
    extern __shared__ __align__(16) uint32_t buf[];

    const int b  = blockIdx.z;
    const int n0 = blockIdx.x * 128;
    const int m0 = blockIdx.y * 128;
    const int tid = threadIdx.x;
    const int wid = tid >> 5, lane = tid & 31;
    const int wm0 = (wid >> 2) * 64, wn0 = (wid & 3) * 32;
    const int row = lane >> 2, colk = lane & 3;

    const uint32_t* yb = g_y16 + (size_t)b * 128 * NPIX;
    const uint32_t sbase = smem_u32(buf);

    auto load_tile = [&](int kt, int stage) {
        const int kw0 = kt * 16;
        const uint32_t As = sbase + stage * STAGE_W * 4;
        const uint32_t Bs = As + AS_SZ * 4;
        #pragma unroll
        for (int j = 0; j < 2; j++) {
            int idx = tid + 256 * j;
            int ar = idx >> 2, ac = (idx & 3) * 4;
            cp16(As + (ar * AS_W + ac) * 4, g_wq16 + (size_t)(m0 + ar) * 128 + kw0 + ac);
        }
        #pragma unroll
        for (int j = 0; j < 2; j++) {
            int idx = tid + 256 * j;
            int bk = idx >> 5, bnc = (idx & 31) * 4;
            cp16(Bs + (bk * BS_W + bnc) * 4, yb + (size_t)(kw0 + bk) * NPIX + n0 + bnc);
        }
    };

    float acc[4][4][4];
    #pragma unroll
    for (int mt = 0; mt < 4; mt++)
        #pragma unroll
        for (int nt = 0; nt < 4; nt++)
            #pragma unroll
            for (int i = 0; i < 4; i++) acc[mt][nt][i] = 0.f;

    load_tile(0, 0); CP_COMMIT();
    load_tile(1, 1); CP_COMMIT();
    load_tile(2, 2); CP_COMMIT();

    #pragma unroll
    for (int kt = 0; kt < 8; kt++) {
        CP_WAIT2();
        __syncthreads();
        const int st = kt % 3;
        const uint32_t* As = buf + st * STAGE_W;
        const uint32_t* Bs = As + AS_SZ;
        gemm_ktile16(As, Bs, wm0, wn0, row, colk, acc);
        __syncthreads();
        if (kt + 3 < 8) load_tile(kt + 3, st);
        CP_COMMIT();
    }

    // Epilogue: pair adjacent o rows via shfl, write packed fp16 [b][c2][n].
    uint32_t* outb = g_qkv16 + (size_t)b * 384 * NPIX;
    const bool evenrow = ((row & 1) == 0);
    #pragma unroll
    for (int mt = 0; mt < 4; mt++) {
        #pragma unroll
        for (int nt = 0; nt < 4; nt++) {
            const int o = m0 + wm0 + mt * 16 + row;
            const int n = n0 + wn0 + nt * 8 + 2 * colk;
            float p0 = __shfl_down_sync(0xFFFFFFFFu, acc[mt][nt][0], 4);
            float p1 = __shfl_down_sync(0xFFFFFFFFu, acc[mt][nt][1], 4);
            float p2 = __shfl_down_sync(0xFFFFFFFFu, acc[mt][nt][2], 4);
            float p3 = __shfl_down_sync(0xFFFFFFFFu, acc[mt][nt][3], 4);
            if (evenrow) {
                uint2 w0 = make_uint2(packh2(acc[mt][nt][0], p0),
                                      packh2(acc[mt][nt][1], p1));
                *(uint2*)(outb + (size_t)(o >> 1) * NPIX + n) = w0;
                uint2 w1 = make_uint2(packh2(acc[mt][nt][2], p2),
                                      packh2(acc[mt][nt][3], p3));
                *(uint2*)(outb + (size_t)((o >> 1) + 4) * NPIX + n) = w1;
            }
        }
    }
}

// ---------------------------------------------------------------------------
// Kernel B: dilated local attention on packed fp16 qkv.
// 128-thread blocks, 5 CTAs/SM. 2 pixels/thread; hd halves across lane pairs.
// ---------------------------------------------------------------------------
__global__ __launch_bounds__(128, 5) void attn_kernel()
{
    const int tid  = threadIdx.x;
    const int wid  = tid >> 5, lane = tid & 31;
    const int half = lane >> 4;
    const int pp   = blockIdx.x * 64 + wid * 16 + (lane & 15);
    const int n    = pp * 2;
    const int dh   = blockIdx.y;
    const int dil  = dh >> 2;
    const int head = dh & 3;
    const int b    = blockIdx.z;
    const int d    = dil ? 3 : 2;

    const int r = n / 80;
    const int c = n % 80;

    const uint32_t* qb = g_qkv16
        + ((size_t)(b * 384 + dil * 64 + head * 16 + half * 8)) * NPIX + n;
    const uint32_t* kb = qb + (size_t)128 * NPIX;
    const uint32_t* vb = qb + (size_t)256 * NPIX;

    float2 qx[8], qy[8];
    #pragma unroll
    for (int j = 0; j < 8; j++) {
        uint2 w = *(const uint2*)(qb + j * NPIX);
        qx[j] = unpackh2(w.x);
        qy[j] = unpackh2(w.y);
    }

    float scx[9], scy[9];
    #pragma unroll
    for (int jj = 0; jj < 9; jj++) {
        const int di = jj / 3 - 1, dj = jj % 3 - 1;
        const int rr = r + di * d;
        const int cc0 = c + dj * d, cc1 = cc0 + 1;
        const bool v0 = (cc0 >= 0 && cc0 < 80);
        const bool v1 = (cc1 >= 0 && cc1 < 80);
        float sx = 0.f, sy = 0.f;
        if (rr >= 0 && rr < 80 && (v0 || v1)) {
            const int off = di * d * 80 + dj * d;
            const uint32_t* kp = kb + off;
            if ((off & 1) == 0) {
                #pragma unroll
                for (int j = 0; j < 8; j++) {
                    uint2 w = *(const uint2*)(kp + j * NPIX);
                    float2 k0 = unpackh2(w.x), k1 = unpackh2(w.y);
                    sx = fmaf(qx[j].x, k0.x, sx); sx = fmaf(qx[j].y, k0.y, sx);
                    sy = fmaf(qy[j].x, k1.x, sy); sy = fmaf(qy[j].y, k1.y, sy);
                }
            } else {
                #pragma unroll
                for (int j = 0; j < 8; j++) {
                    float2 k0 = unpackh2(kp[j * NPIX]);
                    float2 k1 = unpackh2(kp[j * NPIX + 1]);
                    sx = fmaf(qx[j].x, k0.x, sx); sx = fmaf(qx[j].y, k0.y, sx);
                    sy = fmaf(qy[j].x, k1.x, sy); sy = fmaf(qy[j].y, k1.y, sy);
                }
            }
            if (!v0) sx = 0.f;
            if (!v1) sy = 0.f;
        }
        sx += __shfl_xor_sync(0xFFFFFFFFu, sx, 16);
        sy += __shfl_xor_sync(0xFFFFFFFFu, sy, 16);
        scx[jj] = sx * SCALE;
        scy[jj] = sy * SCALE;
    }

    float mx = scx[0], my = scy[0];
    #pragma unroll
    for (int jj = 1; jj < 9; jj++) { mx = fmaxf(mx, scx[jj]); my = fmaxf(my, scy[jj]); }
    float sumx = 0.f, sumy = 0.f;
    #pragma unroll
    for (int jj = 0; jj < 9; jj++) {
        scx[jj] = __expf(scx[jj] - mx); sumx += scx[jj];
        scy[jj] = __expf(scy[jj] - my); sumy += scy[jj];
    }
    const float invx = 1.f / sumx, invy = 1.f / sumy;

    float2 ox[8], oy[8];
    #pragma unroll
    for (int j = 0; j < 8; j++) { ox[j] = make_float2(0.f, 0.f); oy[j] = make_float2(0.f, 0.f); }

    #pragma unroll
    for (int jj = 0; jj < 9; jj++) {
        const int di = jj / 3 - 1, dj = jj % 3 - 1;
        const int rr = r + di * d;
        const int cc0 = c + dj * d, cc1 = cc0 + 1;
        const bool v0 = (cc0 >= 0 && cc0 < 80);
        const bool v1 = (cc1 >= 0 && cc1 < 80);
        if (rr >= 0 && rr < 80 && (v0 || v1)) {
            const int off = di * d * 80 + dj * d;
            const float px = v0 ? scx[jj] * invx : 0.f;
            const float py = v1 ? scy[jj] * invy : 0.f;
            const uint32_t* vp = vb + off;
            if ((off & 1) == 0) {
                #pragma unroll
                for (int j = 0; j < 8; j++) {
                    uint2 w = *(const uint2*)(vp + j * NPIX);
                    float2 a0 = unpackh2(w.x), a1 = unpackh2(w.y);
                    ox[j].x = fmaf(px, a0.x, ox[j].x); ox[j].y = fmaf(px, a0.y, ox[j].y);
                    oy[j].x = fmaf(py, a1.x, oy[j].x); oy[j].y = fmaf(py, a1.y, oy[j].y);
                }
            } else {
                #pragma unroll
                for (int j = 0; j < 8; j++) {
                    float2 a0 = unpackh2(vp[j * NPIX]);
                    float2 a1 = unpackh2(vp[j * NPIX + 1]);
                    ox[j].x = fmaf(px, a0.x, ox[j].x); ox[j].y = fmaf(px, a0.y, ox[j].y);
                    oy[j].x = fmaf(py, a1.x, oy[j].x); oy[j].y = fmaf(py, a1.y, oy[j].y);
                }
            }
        }
    }

    uint32_t* ob = g_attn16
        + ((size_t)(b * 128 + dil * 64 + head * 16 + half * 8)) * NPIX + n;
    #pragma unroll
    for (int j = 0; j < 8; j++) {
        uint2 w = make_uint2(packh2(ox[j].x, ox[j].y), packh2(oy[j].x, oy[j].y));
        *(uint2*)(ob + (size_t)j * NPIX) = w;
    }
}

// ---------------------------------------------------------------------------
// Kernel C: proj (fp16 MMA), 256 threads, 3-stage pipeline, fused epilogue.
// ---------------------------------------------------------------------------
__global__ __launch_bounds__(256, 2) void proj_kernel(const float* __restrict__ bias,
                                                      const float* __restrict__ rgb,
                                                      const float* __restrict__ ir,
                                                      float* __restrict__ out)
{
    extern __shared__ __align__(16) uint32_t buf[];

    const int b  = blockIdx.z;
    const int n0 = blockIdx.x * 128;
    const int m0 = blockIdx.y * 128;
    const int tid = threadIdx.x;
    const int wid = tid >> 5, lane = tid & 31;
    const int wm0 = (wid >> 2) * 64, wn0 = (wid & 3) * 32;
    const int row = lane >> 2, colk = lane & 3;

    const uint32_t* ab = g_attn16 + (size_t)b * 128 * NPIX;
    const uint32_t sbase = smem_u32(buf);

    auto load_tile = [&](int kt, int stage) {
        const int kw0 = kt * 16;
        const uint32_t As = sbase + stage * STAGE_W * 4;
        const uint32_t Bs = As + AS_SZ * 4;
        #pragma unroll
        for (int j = 0; j < 2; j++) {
            int idx = tid + 256 * j;
            int ar = idx >> 2, ac = (idx & 3) * 4;
            cp16(As + (ar * AS_W + ac) * 4, g_wp16 + (size_t)(m0 + ar) * 128 + kw0 + ac);
        }
        #pragma unroll
        for (int j = 0; j < 2; j++) {
            int idx = tid + 256 * j;
            int bk = idx >> 5, bnc = (idx & 31) * 4;
            cp16(Bs + (bk * BS_W + bnc) * 4, ab + (size_t)(kw0 + bk) * NPIX + n0 + bnc);
        }
    };

    float acc[4][4][4];
    #pragma unroll
    for (int mt = 0; mt < 4; mt++)
        #pragma unroll
        for (int nt = 0; nt < 4; nt++)
            #pragma unroll
            for (int i = 0; i < 4; i++) acc[mt][nt][i] = 0.f;

    load_tile(0, 0); CP_COMMIT();
    load_tile(1, 1); CP_COMMIT();
    load_tile(2, 2); CP_COMMIT();

    #pragma unroll
    for (int kt = 0; kt < 8; kt++) {
        CP_WAIT2();
        __syncthreads();
        const int st = kt % 3;
        const uint32_t* As = buf + st * STAGE_W;
        const uint32_t* Bs = As + AS_SZ;
        gemm_ktile16(As, Bs, wm0, wn0, row, colk, acc);
        __syncthreads();
        if (kt + 3 < 8) load_tile(kt + 3, st);
        CP_COMMIT();
    }

    const float* resb = ((m0 == 0) ? rgb : ir) + (size_t)b * 128 * NPIX;
    float* outb = out + (size_t)b * NPIX * 256;

    #pragma unroll
    for (int mt = 0; mt < 4; mt++) {
        const int o_lo = m0 + wm0 + mt * 16 + row;
        const int o_hi = o_lo + 8;
        const float bias_lo = __ldg(bias + o_lo);
        const float bias_hi = __ldg(bias + o_hi);
        const float* res_lo = resb + (size_t)(o_lo & 127) * NPIX;
        const float* res_hi = resb + (size_t)(o_hi & 127) * NPIX;
        #pragma unroll
        for (int nt = 0; nt < 4; nt++) {
            const int n = n0 + wn0 + nt * 8 + 2 * colk;
            outb[(size_t)n * 256 + o_lo]       = acc[mt][nt][0] + bias_lo + res_lo[n];
            outb[(size_t)(n + 1) * 256 + o_lo] = acc[mt][nt][1] + bias_lo + res_lo[n + 1];
            outb[(size_t)n * 256 + o_hi]       = acc[mt][nt][2] + bias_hi + res_hi[n];
            outb[(size_t)(n + 1) * 256 + o_hi] = acc[mt][nt][3] + bias_hi + res_hi[n + 1];
        }
    }
}

// ---------------------------------------------------------------------------
extern "C" void kernel_launch(void* const* d_in, const int* in_sizes, int n_in,
                              void* d_out, int out_size)
{
    const float* rgb    = (const float*)d_in[0];
    const float* ir     = (const float*)d_in[1];
    const float* w_qkv  = (const float*)d_in[2];
    const float* w_proj = (const float*)d_in[3];
    const float* b_proj = (const float*)d_in[4];
    float* out = (float*)d_out;

    cudaFuncSetAttribute(qkv_gemm, cudaFuncAttributeMaxDynamicSharedMemorySize, SMEM_BYTES);
    cudaFuncSetAttribute(proj_kernel, cudaFuncAttributeMaxDynamicSharedMemorySize, SMEM_BYTES);

    conv_w<<<1024, 128>>>(w_qkv, w_proj);
    conv_y16<<<dim3(25, 128, 4), 256>>>(rgb, ir);
    qkv_gemm<<<dim3(50, 6, 4), 256, SMEM_BYTES>>>();
    attn_kernel<<<dim3(50, 8, 4), 128>>>();
    proj_kernel<<<dim3(50, 2, 4), 256, SMEM_BYTES>>>(b_proj, rgb, ir, out);
}

// round 17
// speedup vs baseline: 2.2329x; 1.0176x over previous
#include <cuda_runtime.h>
#include <cstdint>
#include <cuda_fp16.h>

#define NPIX   6400
#define SCALE  0.17677669529663687f   // 32^-0.5

// Scratch (device globals), all fp16 channel-pair packed: word (c2, n) =
// half2(ch 2*c2, ch 2*c2+1) at pixel n. +16 words padding for vector overread.
__device__ __align__(16) uint32_t g_qkv16 [4 * 384 * 6400 + 16]; // q|k|v planes
__device__ __align__(16) uint32_t g_attn16[4 * 128 * 6400 + 16];
__device__ __align__(16) uint32_t g_y16   [4 * 128 * 6400];
__device__ uint32_t g_wq16[768 * 128];   // packed fp16, k-interleaved
__device__ uint32_t g_wp16[256 * 128];

// ---------------------------------------------------------------------------
// Helpers (sm_80-class PTX only: family-safe on compute_103)
// ---------------------------------------------------------------------------
__device__ __forceinline__ uint32_t smem_u32(const void* p) {
    uint32_t a;
    asm("{ .reg .u64 t; cvta.to.shared.u64 t, %1; cvt.u32.u64 %0, t; }" : "=r"(a) : "l"(p));
    return a;
}
__device__ __forceinline__ void cp16(uint32_t dst, const void* src) {
    asm volatile("cp.async.cg.shared.global [%0], [%1], 16;" :: "r"(dst), "l"(src));
}
#define CP_COMMIT() asm volatile("cp.async.commit_group;" ::: "memory")
#define CP_WAIT2()  asm volatile("cp.async.wait_group 2;" ::: "memory")

__device__ __forceinline__ uint32_t packh2(float a, float b) {
    __half2 h = __floats2half2_rn(a, b);          // a -> low half
    return *reinterpret_cast<uint32_t*>(&h);
}
__device__ __forceinline__ float2 unpackh2(uint32_t w) {
    return __half22float2(*reinterpret_cast<__half2*>(&w));
}
__device__ __forceinline__ void mma_f16(float c[4],
                                        uint32_t a0, uint32_t a1, uint32_t a2, uint32_t a3,
                                        uint32_t b0, uint32_t b1) {
    asm volatile("mma.sync.aligned.m16n8k16.row.col.f32.f16.f16.f32 "
                 "{%0,%1,%2,%3}, {%4,%5,%6,%7}, {%8,%9}, {%0,%1,%2,%3};"
                 : "+f"(c[0]), "+f"(c[1]), "+f"(c[2]), "+f"(c[3])
                 : "r"(a0), "r"(a1), "r"(a2), "r"(a3), "r"(b0), "r"(b1));
}

// Smem (per stage, uint32 words): A [128 o][24] (16 words + pad), B [16][136]
#define AS_W    24
#define AS_SZ   (128 * AS_W)
#define BS_W    136
#define BS_SZ   (16 * BS_W)
#define STAGE_W (AS_SZ + BS_SZ)          // 5248 words = 20992 B
#define SMEM_BYTES (3 * STAGE_W * 4)     // 62976 B (3 stages)

// ---------------------------------------------------------------------------
// Fused prologue.
// blockIdx.y < 128 : y = concat(rgb, ir) -> packed fp16 [b][c2][n]
// blockIdx.y == 128: weights -> packed fp16, 8-group k-interleaved.
//   Parallelized across ALL (x, z) blocks: 100 blocks x 256 thr cover
//   1024 rows x 128 words with coalesced reads (~6 words per thread).
// ---------------------------------------------------------------------------
__global__ __launch_bounds__(256) void conv_fused(const float* __restrict__ rgb,
                                                  const float* __restrict__ ir,
                                                  const float* __restrict__ wq,
                                                  const float* __restrict__ wp)
{
    const int c2 = blockIdx.y;
    if (c2 < 128) {
        const int n = blockIdx.x * 256 + threadIdx.x;
        const int b = blockIdx.z;
        const float* src = (c2 < 64)
            ? rgb + ((size_t)b * 128 + 2 * c2) * NPIX
            : ir  + ((size_t)b * 128 + 2 * (c2 - 64)) * NPIX;
        g_y16[((size_t)b * 128 + c2) * NPIX + n] = packh2(src[n], src[NPIX + n]);
    } else {
        // weight strip: linear word index over [1024 rows][128 words]
        const int base = (blockIdx.z * 25 + blockIdx.x) * 256 + threadIdx.x;
        const int stride = 25 * 4 * 256;                  // 25600 threads
        for (int w = base; w < 1024 * 128; w += stride) {
            const int row = w >> 7;
            const int j   = w & 127;
            const int jp  = (j & ~7) | (((j & 3) << 1) | ((j >> 2) & 1));
            if (row < 768)
                g_wq16[row * 128 + jp] = packh2(wq[row * 256 + 2 * j],
                                                wq[row * 256 + 2 * j + 1]);
            else
                g_wp16[(row - 768) * 128 + jp] = packh2(wp[(row - 768) * 256 + 2 * j],
                                                        wp[(row - 768) * 256 + 2 * j + 1]);
        }
    }
}

// ---------------------------------------------------------------------------
// GEMM k-tile (32 k = 16 words): warp grid 2(m) x 4(n), warp tile 64 x 32.
// ---------------------------------------------------------------------------
__device__ __forceinline__ void gemm_ktile16(const uint32_t* As, const uint32_t* Bs,
                                             int wm0, int wn0, int row, int colk,
                                             float acc[4][4][4]) {
    #pragma unroll
    for (int ks = 0; ks < 2; ks++) {
        const int kb = ks * 8;
        uint32_t a[4][4], bfr[4][2];
        #pragma unroll
        for (int mt = 0; mt < 4; mt++) {
            const uint32_t* ab = As + (wm0 + mt * 16 + row) * AS_W + kb + 2 * colk;
            uint2 lo = *(const uint2*)ab;
            uint2 hi = *(const uint2*)(ab + 8 * AS_W);
            a[mt][0] = lo.x; a[mt][1] = hi.x; a[mt][2] = lo.y; a[mt][3] = hi.y;
        }
        #pragma unroll
        for (int nt = 0; nt < 4; nt++) {
            const uint32_t* bb = Bs + (kb + colk) * BS_W + wn0 + nt * 8 + row;
            bfr[nt][0] = bb[0];
            bfr[nt][1] = bb[4 * BS_W];
        }
        #pragma unroll
        for (int mt = 0; mt < 4; mt++)
            #pragma unroll
            for (int nt = 0; nt < 4; nt++)
                mma_f16(acc[mt][nt], a[mt][0], a[mt][1], a[mt][2], a[mt][3],
                        bfr[nt][0], bfr[nt][1]);
    }
}

// ---------------------------------------------------------------------------
// Kernel A: qkv (fp16 MMA), 256 threads / 128x128 tile, 3-stage pipeline.
// ---------------------------------------------------------------------------
__global__ __launch_bounds__(256, 2) void qkv_gemm()
{
    extern __shared__ __align__(16) uint32_t buf[];

    const int b  = blockIdx.z;
    const int n0 = blockIdx.x * 128;
    const int m0 = blockIdx.y * 128;
    const int tid = threadIdx.x;
    const int wid = tid >> 5, lane = tid & 31;
    const int wm0 = (wid >> 2) * 64, wn0 = (wid & 3) * 32;
    const int row = lane >> 2, colk = lane & 3;

    const uint32_t* yb = g_y16 + (size_t)b * 128 * NPIX;
    const uint32_t sbase = smem_u32(buf);

    auto load_tile = [&](int kt, int stage) {
        const int kw0 = kt * 16;
        const uint32_t As = sbase + stage * STAGE_W * 4;
        const uint32_t Bs = As + AS_SZ * 4;
        #pragma unroll
        for (int j = 0; j < 2; j++) {
            int idx = tid + 256 * j;
            int ar = idx >> 2, ac = (idx & 3) * 4;
            cp16(As + (ar * AS_W + ac) * 4, g_wq16 + (size_t)(m0 + ar) * 128 + kw0 + ac);
        }
        #pragma unroll
        for (int j = 0; j < 2; j++) {
            int idx = tid + 256 * j;
            int bk = idx >> 5, bnc = (idx & 31) * 4;
            cp16(Bs + (bk * BS_W + bnc) * 4, yb + (size_t)(kw0 + bk) * NPIX + n0 + bnc);
        }
    };

    float acc[4][4][4];
    #pragma unroll
    for (int mt = 0; mt < 4; mt++)
        #pragma unroll
        for (int nt = 0; nt < 4; nt++)
            #pragma unroll
            for (int i = 0; i < 4; i++) acc[mt][nt][i] = 0.f;

    load_tile(0, 0); CP_COMMIT();
    load_tile(1, 1); CP_COMMIT();
    load_tile(2, 2); CP_COMMIT();

    #pragma unroll
    for (int kt = 0; kt < 8; kt++) {
        CP_WAIT2();
        __syncthreads();
        const int st = kt % 3;
        const uint32_t* As = buf + st * STAGE_W;
        const uint32_t* Bs = As + AS_SZ;
        gemm_ktile16(As, Bs, wm0, wn0, row, colk, acc);
        __syncthreads();
        if (kt + 3 < 8) load_tile(kt + 3, st);
        CP_COMMIT();
    }

    // Epilogue: pair adjacent o rows via shfl, write packed fp16 [b][c2][n].
    uint32_t* outb = g_qkv16 + (size_t)b * 384 * NPIX;
    const bool evenrow = ((row & 1) == 0);
    #pragma unroll
    for (int mt = 0; mt < 4; mt++) {
        #pragma unroll
        for (int nt = 0; nt < 4; nt++) {
            const int o = m0 + wm0 + mt * 16 + row;
            const int n = n0 + wn0 + nt * 8 + 2 * colk;
            float p0 = __shfl_down_sync(0xFFFFFFFFu, acc[mt][nt][0], 4);
            float p1 = __shfl_down_sync(0xFFFFFFFFu, acc[mt][nt][1], 4);
            float p2 = __shfl_down_sync(0xFFFFFFFFu, acc[mt][nt][2], 4);
            float p3 = __shfl_down_sync(0xFFFFFFFFu, acc[mt][nt][3], 4);
            if (evenrow) {
                uint2 w0 = make_uint2(packh2(acc[mt][nt][0], p0),
                                      packh2(acc[mt][nt][1], p1));
                *(uint2*)(outb + (size_t)(o >> 1) * NPIX + n) = w0;
                uint2 w1 = make_uint2(packh2(acc[mt][nt][2], p2),
                                      packh2(acc[mt][nt][3], p3));
                *(uint2*)(outb + (size_t)((o >> 1) + 4) * NPIX + n) = w1;
            }
        }
    }
}

// ---------------------------------------------------------------------------
// Kernel B: dilated local attention on packed fp16 qkv.
// 128-thread blocks, 5 CTAs/SM. 2 pixels/thread; hd halves across lane pairs.
// ---------------------------------------------------------------------------
__global__ __launch_bounds__(128, 5) void attn_kernel()
{
    const int tid  = threadIdx.x;
    const int wid  = tid >> 5, lane = tid & 31;
    const int half = lane >> 4;
    const int pp   = blockIdx.x * 64 + wid * 16 + (lane & 15);
    const int n    = pp * 2;
    const int dh   = blockIdx.y;
    const int dil  = dh >> 2;
    const int head = dh & 3;
    const int b    = blockIdx.z;
    const int d    = dil ? 3 : 2;

    const int r = n / 80;
    const int c = n % 80;

    const uint32_t* qb = g_qkv16
        + ((size_t)(b * 384 + dil * 64 + head * 16 + half * 8)) * NPIX + n;
    const uint32_t* kb = qb + (size_t)128 * NPIX;
    const uint32_t* vb = qb + (size_t)256 * NPIX;

    float2 qx[8], qy[8];
    #pragma unroll
    for (int j = 0; j < 8; j++) {
        uint2 w = *(const uint2*)(qb + j * NPIX);
        qx[j] = unpackh2(w.x);
        qy[j] = unpackh2(w.y);
    }

    float scx[9], scy[9];
    #pragma unroll
    for (int jj = 0; jj < 9; jj++) {
        const int di = jj / 3 - 1, dj = jj % 3 - 1;
        const int rr = r + di * d;
        const int cc0 = c + dj * d, cc1 = cc0 + 1;
        const bool v0 = (cc0 >= 0 && cc0 < 80);
        const bool v1 = (cc1 >= 0 && cc1 < 80);
        float sx = 0.f, sy = 0.f;
        if (rr >= 0 && rr < 80 && (v0 || v1)) {
            const int off = di * d * 80 + dj * d;
            const uint32_t* kp = kb + off;
            if ((off & 1) == 0) {
                #pragma unroll
                for (int j = 0; j < 8; j++) {
                    uint2 w = *(const uint2*)(kp + j * NPIX);
                    float2 k0 = unpackh2(w.x), k1 = unpackh2(w.y);
                    sx = fmaf(qx[j].x, k0.x, sx); sx = fmaf(qx[j].y, k0.y, sx);
                    sy = fmaf(qy[j].x, k1.x, sy); sy = fmaf(qy[j].y, k1.y, sy);
                }
            } else {
                #pragma unroll
                for (int j = 0; j < 8; j++) {
                    float2 k0 = unpackh2(kp[j * NPIX]);
                    float2 k1 = unpackh2(kp[j * NPIX + 1]);
                    sx = fmaf(qx[j].x, k0.x, sx); sx = fmaf(qx[j].y, k0.y, sx);
                    sy = fmaf(qy[j].x, k1.x, sy); sy = fmaf(qy[j].y, k1.y, sy);
                }
            }
            if (!v0) sx = 0.f;
            if (!v1) sy = 0.f;
        }
        sx += __shfl_xor_sync(0xFFFFFFFFu, sx, 16);
        sy += __shfl_xor_sync(0xFFFFFFFFu, sy, 16);
        scx[jj] = sx * SCALE;
        scy[jj] = sy * SCALE;
    }

    float mx = scx[0], my = scy[0];
    #pragma unroll
    for (int jj = 1; jj < 9; jj++) { mx = fmaxf(mx, scx[jj]); my = fmaxf(my, scy[jj]); }
    float sumx = 0.f, sumy = 0.f;
    #pragma unroll
    for (int jj = 0; jj < 9; jj++) {
        scx[jj] = __expf(scx[jj] - mx); sumx += scx[jj];
        scy[jj] = __expf(scy[jj] - my); sumy += scy[jj];
    }
    const float invx = 1.f / sumx, invy = 1.f / sumy;

    float2 ox[8], oy[8];
    #pragma unroll
    for (int j = 0; j < 8; j++) { ox[j] = make_float2(0.f, 0.f); oy[j] = make_float2(0.f, 0.f); }

    #pragma unroll
    for (int jj = 0; jj < 9; jj++) {
        const int di = jj / 3 - 1, dj = jj % 3 - 1;
        const int rr = r + di * d;
        const int cc0 = c + dj * d, cc1 = cc0 + 1;
        const bool v0 = (cc0 >= 0 && cc0 < 80);
        const bool v1 = (cc1 >= 0 && cc1 < 80);
        if (rr >= 0 && rr < 80 && (v0 || v1)) {
            const int off = di * d * 80 + dj * d;
            const float px = v0 ? scx[jj] * invx : 0.f;
            const float py = v1 ? scy[jj] * invy : 0.f;
            const uint32_t* vp = vb + off;
            if ((off & 1) == 0) {
                #pragma unroll
                for (int j = 0; j < 8; j++) {
                    uint2 w = *(const uint2*)(vp + j * NPIX);
                    float2 a0 = unpackh2(w.x), a1 = unpackh2(w.y);
                    ox[j].x = fmaf(px, a0.x, ox[j].x); ox[j].y = fmaf(px, a0.y, ox[j].y);
                    oy[j].x = fmaf(py, a1.x, oy[j].x); oy[j].y = fmaf(py, a1.y, oy[j].y);
                }
            } else {
                #pragma unroll
                for (int j = 0; j < 8; j++) {
                    float2 a0 = unpackh2(vp[j * NPIX]);
                    float2 a1 = unpackh2(vp[j * NPIX + 1]);
                    ox[j].x = fmaf(px, a0.x, ox[j].x); ox[j].y = fmaf(px, a0.y, ox[j].y);
                    oy[j].x = fmaf(py, a1.x, oy[j].x); oy[j].y = fmaf(py, a1.y, oy[j].y);
                }
            }
        }
    }

    uint32_t* ob = g_attn16
        + ((size_t)(b * 128 + dil * 64 + head * 16 + half * 8)) * NPIX + n;
    #pragma unroll
    for (int j = 0; j < 8; j++) {
        uint2 w = make_uint2(packh2(ox[j].x, ox[j].y), packh2(oy[j].x, oy[j].y));
        *(uint2*)(ob + (size_t)j * NPIX) = w;
    }
}

// ---------------------------------------------------------------------------
// Kernel C: proj (fp16 MMA), 256 threads, 3-stage pipeline, fused epilogue.
// ---------------------------------------------------------------------------
__global__ __launch_bounds__(256, 2) void proj_kernel(const float* __restrict__ bias,
                                                      const float* __restrict__ rgb,
                                                      const float* __restrict__ ir,
                                                      float* __restrict__ out)
{
    extern __shared__ __align__(16) uint32_t buf[];

    const int b  = blockIdx.z;
    const int n0 = blockIdx.x * 128;
    const int m0 = blockIdx.y * 128;
    const int tid = threadIdx.x;
    const int wid = tid >> 5, lane = tid & 31;
    const int wm0 = (wid >> 2) * 64, wn0 = (wid & 3) * 32;
    const int row = lane >> 2, colk = lane & 3;

    const uint32_t* ab = g_attn16 + (size_t)b * 128 * NPIX;
    const uint32_t sbase = smem_u32(buf);

    auto load_tile = [&](int kt, int stage) {
        const int kw0 = kt * 16;
        const uint32_t As = sbase + stage * STAGE_W * 4;
        const uint32_t Bs = As + AS_SZ * 4;
        #pragma unroll
        for (int j = 0; j < 2; j++) {
            int idx = tid + 256 * j;
            int ar = idx >> 2, ac = (idx & 3) * 4;
            cp16(As + (ar * AS_W + ac) * 4, g_wp16 + (size_t)(m0 + ar) * 128 + kw0 + ac);
        }
        #pragma unroll
        for (int j = 0; j < 2; j++) {
            int idx = tid + 256 * j;
            int bk = idx >> 5, bnc = (idx & 31) * 4;
            cp16(Bs + (bk * BS_W + bnc) * 4, ab + (size_t)(kw0 + bk) * NPIX + n0 + bnc);
        }
    };

    float acc[4][4][4];
    #pragma unroll
    for (int mt = 0; mt < 4; mt++)
        #pragma unroll
        for (int nt = 0; nt < 4; nt++)
            #pragma unroll
            for (int i = 0; i < 4; i++) acc[mt][nt][i] = 0.f;

    load_tile(0, 0); CP_COMMIT();
    load_tile(1, 1); CP_COMMIT();
    load_tile(2, 2); CP_COMMIT();

    #pragma unroll
    for (int kt = 0; kt < 8; kt++) {
        CP_WAIT2();
        __syncthreads();
        const int st = kt % 3;
        const uint32_t* As = buf + st * STAGE_W;
        const uint32_t* Bs = As + AS_SZ;
        gemm_ktile16(As, Bs, wm0, wn0, row, colk, acc);
        __syncthreads();
        if (kt + 3 < 8) load_tile(kt + 3, st);
        CP_COMMIT();
    }

    const float* resb = ((m0 == 0) ? rgb : ir) + (size_t)b * 128 * NPIX;
    float* outb = out + (size_t)b * NPIX * 256;

    #pragma unroll
    for (int mt = 0; mt < 4; mt++) {
        const int o_lo = m0 + wm0 + mt * 16 + row;
        const int o_hi = o_lo + 8;
        const float bias_lo = __ldg(bias + o_lo);
        const float bias_hi = __ldg(bias + o_hi);
        const float* res_lo = resb + (size_t)(o_lo & 127) * NPIX;
        const float* res_hi = resb + (size_t)(o_hi & 127) * NPIX;
        #pragma unroll
        for (int nt = 0; nt < 4; nt++) {
            const int n = n0 + wn0 + nt * 8 + 2 * colk;
            outb[(size_t)n * 256 + o_lo]       = acc[mt][nt][0] + bias_lo + res_lo[n];
            outb[(size_t)(n + 1) * 256 + o_lo] = acc[mt][nt][1] + bias_lo + res_lo[n + 1];
            outb[(size_t)n * 256 + o_hi]       = acc[mt][nt][2] + bias_hi + res_hi[n];
            outb[(size_t)(n + 1) * 256 + o_hi] = acc[mt][nt][3] + bias_hi + res_hi[n + 1];
        }
    }
}

// ---------------------------------------------------------------------------
extern "C" void kernel_launch(void* const* d_in, const int* in_sizes, int n_in,
                              void* d_out, int out_size)
{
    const float* rgb    = (const float*)d_in[0];
    const float* ir     = (const float*)d_in[1];
    const float* w_qkv  = (const float*)d_in[2];
    const float* w_proj = (const float*)d_in[3];
    const float* b_proj = (const float*)d_in[4];
    float* out = (float*)d_out;

    cudaFuncSetAttribute(qkv_gemm, cudaFuncAttributeMaxDynamicSharedMemorySize, SMEM_BYTES);
    cudaFuncSetAttribute(proj_kernel, cudaFuncAttributeMaxDynamicSharedMemorySize, SMEM_BYTES);

    conv_fused<<<dim3(25, 129, 4), 256>>>(rgb, ir, w_qkv, w_proj);
    qkv_gemm<<<dim3(50, 6, 4), 256, SMEM_BYTES>>>();
    attn_kernel<<<dim3(50, 8, 4), 128>>>();
    proj_kernel<<<dim3(50, 2, 4), 256, SMEM_BYTES>>>(b_proj, rgb, ir, out);
}